// round 11
// baseline (speedup 1.0000x reference)
#include <cuda_runtime.h>
#include <cuda_bf16.h>
#include <math.h>

#define NMAX 100000
#define EMAX 1600000
#define H 128
#define GG 64
#define BN_EPS 1e-5f
#define SCAN_B 1024
#define SPAD 40   // smem row stride (bf16 elems) -> conflict-free frag loads

// ---------------- scratch ----------------------------------------------------
__device__ float g_h[NMAX * H];
__device__ float g_z[NMAX * H];
__device__ float g_agg[NMAX * H];
__device__ float g_dinv[NMAX];
__device__ float g_alog[NMAX];
__device__ float g_stats[2 * H];
__device__ float g_part[256];
__device__ float g_scal[4];
__device__ float g_pooled[GG * H];
__device__ float g_counts[GG];
__device__ int   g_idxmode;
__device__ int   g_E;
__device__ int g_cnt[NMAX];
__device__ int g_cur[NMAX];
__device__ int g_rexc[NMAX];
__device__ int g_bsum[SCAN_B];
__device__ int g_bsumx[SCAN_B];
__device__ int g_rowstart[NMAX + 1];
__device__ int g_col[EMAX];

// ---------------- dual-dtype index load -------------------------------------
__device__ __forceinline__ int ld_idx(const void* p, long long i) {
    if (g_idxmode) return (int)((const long long*)p)[i];
    return ((const int*)p)[i];
}

__global__ void k_detect(const long long* __restrict__ ei, int n,
                         long long raw, int bytes_mode, long long avail64) {
    int bad = 0;
    int m = (avail64 < 1024) ? (int)avail64 : 1024;
    if (m < 1) m = 1;
    for (int i = threadIdx.x; i < m; i += 32) {
        long long v = ei[i];
        if (v < 0 || v >= (long long)n) bad = 1;
    }
    unsigned anybad = __ballot_sync(0xffffffffu, bad);
    if (threadIdx.x == 0) {
        int mode = (anybad == 0u) ? 1 : 0;
        g_idxmode = mode;
        long long E;
        if (bytes_mode) E = raw / ((mode ? 8 : 4) * 2);
        else            E = raw / 2;
        if (E > EMAX) E = EMAX;
        g_E = (int)E;
    }
}

// ---------------- CSR build --------------------------------------------------
__global__ void k_zero_cnt(int n) {
    int i = blockIdx.x * blockDim.x + threadIdx.x;
    if (i < n) { g_cnt[i] = 0; g_cur[i] = 0; }
}

__global__ void k_hist(const void* __restrict__ ei, int n) {
    int i = blockIdx.x * blockDim.x + threadIdx.x;
    int E = g_E;
    if (i >= E) return;
    int d = ld_idx(ei, (long long)E + i);
    if ((unsigned)d < (unsigned)n) atomicAdd(&g_cnt[d], 1);
}

__global__ void k_scan1(int n) {
    __shared__ int sm[SCAN_B];
    int i = blockIdx.x * SCAN_B + threadIdx.x;
    int v = (i < n) ? g_cnt[i] : 0;
    if (i < n) g_dinv[i] = rsqrtf((float)(v + 1));
    sm[threadIdx.x] = v;
    __syncthreads();
    for (int off = 1; off < SCAN_B; off <<= 1) {
        int t = (threadIdx.x >= off) ? sm[threadIdx.x - off] : 0;
        __syncthreads();
        sm[threadIdx.x] += t;
        __syncthreads();
    }
    if (i < n) g_rexc[i] = sm[threadIdx.x] - v;
    if (threadIdx.x == SCAN_B - 1) g_bsum[blockIdx.x] = sm[threadIdx.x];
}

__global__ void k_scan2(int nb) {
    __shared__ int sm[SCAN_B];
    int v = (threadIdx.x < nb) ? g_bsum[threadIdx.x] : 0;
    sm[threadIdx.x] = v;
    __syncthreads();
    for (int off = 1; off < SCAN_B; off <<= 1) {
        int t = (threadIdx.x >= off) ? sm[threadIdx.x - off] : 0;
        __syncthreads();
        sm[threadIdx.x] += t;
        __syncthreads();
    }
    g_bsumx[threadIdx.x] = sm[threadIdx.x] - v;
}

__global__ void k_scan3(int n) {
    int i = blockIdx.x * SCAN_B + threadIdx.x;
    if (i < n) g_rowstart[i] = g_rexc[i] + g_bsumx[i / SCAN_B];
    if (i == 0) g_rowstart[n] = g_E;
}

__global__ void k_fill(const void* __restrict__ ei, int n) {
    int e = blockIdx.x * blockDim.x + threadIdx.x;
    int E = g_E;
    if (e >= E) return;
    int s = ld_idx(ei, e);
    int d = ld_idx(ei, (long long)E + e);
    if ((unsigned)s >= (unsigned)n || (unsigned)d >= (unsigned)n) return;
    int pos = g_rowstart[d] + atomicAdd(&g_cur[d], 1);
    if (pos >= 0 && pos < EMAX) g_col[pos] = s;
}

// ---------------- split-bf16 tensor-core GEMM --------------------------------
// g_z = A @ W via mma.sync m16n8k16 bf16 with hi/lo split (3 passes).
// SRC==0: A=Ain(x)  SRC==1: A=g_h.
// EPI==0: store g_z. EPI==1: g_alog[row] = sum tanh(z+b1)*w2 + b2 (no z store).
__device__ __forceinline__ void mma_bf16(float* d, const unsigned* a, const unsigned* b) {
    asm volatile(
        "mma.sync.aligned.m16n8k16.row.col.f32.bf16.bf16.f32 "
        "{%0,%1,%2,%3}, {%4,%5,%6,%7}, {%8,%9}, {%0,%1,%2,%3};\n"
        : "+f"(d[0]), "+f"(d[1]), "+f"(d[2]), "+f"(d[3])
        : "r"(a[0]), "r"(a[1]), "r"(a[2]), "r"(a[3]), "r"(b[0]), "r"(b[1]));
}

template <int SRC, int EPI>
__global__ void __launch_bounds__(256, 1)
k_gemm_tc(const float* __restrict__ Ain,
          const float* __restrict__ W,
          const float* __restrict__ bias,
          const float* __restrict__ w2,
          const float* __restrict__ b2,
          int nrows) {
    const float* A = (SRC == 0) ? Ain : (const float*)g_h;
    __shared__ __nv_bfloat16 sAh[128][SPAD], sAl[128][SPAD];
    __shared__ __nv_bfloat16 sBh[128][SPAD], sBl[128][SPAD];
    __shared__ float s_logit[128];

    const int tid  = threadIdx.x;
    const int warp = tid >> 5;
    const int lane = tid & 31;
    const int wr = warp >> 1;           // warp row 0..3
    const int wc = warp & 1;            // warp col 0..1
    const int row0 = wr * 32;
    const int col0 = wc * 64;
    const int g = lane >> 2;            // group id 0..7
    const int t = lane & 3;             // thread in group
    const int block_row = blockIdx.x * 128;

    if (EPI == 1 && tid < 128) s_logit[tid] = 0.0f;

    float acc[2][8][4];
#pragma unroll
    for (int mi = 0; mi < 2; mi++)
#pragma unroll
        for (int ni = 0; ni < 8; ni++)
#pragma unroll
            for (int r = 0; r < 4; r++) acc[mi][ni][r] = 0.0f;

    for (int kc = 0; kc < 4; kc++) {
        // A tile: 128 rows x 32 floats -> split hi/lo
        for (int i = tid; i < 1024; i += 256) {
            int r = i >> 3, c4 = (i & 7) * 4;
            int gr = block_row + r;
            float4 v = make_float4(0.f, 0.f, 0.f, 0.f);
            if (gr < nrows) v = *(const float4*)(A + (size_t)gr * H + kc * 32 + c4);
            float vv[4] = {v.x, v.y, v.z, v.w};
#pragma unroll
            for (int j = 0; j < 4; j++) {
                __nv_bfloat16 hi = __float2bfloat16_rn(vv[j]);
                sAh[r][c4 + j] = hi;
                sAl[r][c4 + j] = __float2bfloat16_rn(vv[j] - __bfloat162float(hi));
            }
        }
        // W tile: 32 rows (k) x 128 cols -> transposed smem [col][k], split
        for (int i = tid; i < 1024; i += 256) {
            int k = i >> 5, c4 = (i & 31) * 4;
            float4 v = *(const float4*)(W + (size_t)(kc * 32 + k) * H + c4);
            float vv[4] = {v.x, v.y, v.z, v.w};
#pragma unroll
            for (int j = 0; j < 4; j++) {
                __nv_bfloat16 hi = __float2bfloat16_rn(vv[j]);
                sBh[c4 + j][k] = hi;
                sBl[c4 + j][k] = __float2bfloat16_rn(vv[j] - __bfloat162float(hi));
            }
        }
        __syncthreads();

#pragma unroll
        for (int ks = 0; ks < 2; ks++) {
            const int kb = ks * 16;
            unsigned ah[2][4], al[2][4];
#pragma unroll
            for (int mi = 0; mi < 2; mi++) {
                int r = row0 + mi * 16 + g;
                ah[mi][0] = *(const unsigned*)&sAh[r][kb + t * 2];
                ah[mi][1] = *(const unsigned*)&sAh[r + 8][kb + t * 2];
                ah[mi][2] = *(const unsigned*)&sAh[r][kb + 8 + t * 2];
                ah[mi][3] = *(const unsigned*)&sAh[r + 8][kb + 8 + t * 2];
                al[mi][0] = *(const unsigned*)&sAl[r][kb + t * 2];
                al[mi][1] = *(const unsigned*)&sAl[r + 8][kb + t * 2];
                al[mi][2] = *(const unsigned*)&sAl[r][kb + 8 + t * 2];
                al[mi][3] = *(const unsigned*)&sAl[r + 8][kb + 8 + t * 2];
            }
#pragma unroll
            for (int ni = 0; ni < 8; ni++) {
                int c = col0 + ni * 8 + g;
                unsigned bh[2], bl[2];
                bh[0] = *(const unsigned*)&sBh[c][kb + t * 2];
                bh[1] = *(const unsigned*)&sBh[c][kb + 8 + t * 2];
                bl[0] = *(const unsigned*)&sBl[c][kb + t * 2];
                bl[1] = *(const unsigned*)&sBl[c][kb + 8 + t * 2];
#pragma unroll
                for (int mi = 0; mi < 2; mi++) {
                    mma_bf16(acc[mi][ni], ah[mi], bh);   // hi*hi
                    mma_bf16(acc[mi][ni], ah[mi], bl);   // hi*lo
                    mma_bf16(acc[mi][ni], al[mi], bh);   // lo*hi
                }
            }
        }
        __syncthreads();
    }

    if (EPI == 0) {
#pragma unroll
        for (int mi = 0; mi < 2; mi++) {
            int r_lo = block_row + row0 + mi * 16 + g;
            int r_hi = r_lo + 8;
#pragma unroll
            for (int ni = 0; ni < 8; ni++) {
                int c = col0 + ni * 8 + t * 2;
                if (r_lo < nrows)
                    *(float2*)(g_z + (size_t)r_lo * H + c) =
                        make_float2(acc[mi][ni][0], acc[mi][ni][1]);
                if (r_hi < nrows)
                    *(float2*)(g_z + (size_t)r_hi * H + c) =
                        make_float2(acc[mi][ni][2], acc[mi][ni][3]);
            }
        }
    } else {
        __syncthreads();   // ensure s_logit zero-init visible
#pragma unroll
        for (int mi = 0; mi < 2; mi++) {
            float p_lo = 0.0f, p_hi = 0.0f;
#pragma unroll
            for (int ni = 0; ni < 8; ni++) {
                int c = col0 + ni * 8 + t * 2;
                float w20 = w2[c], w21 = w2[c + 1];
                float b10 = bias[c], b11 = bias[c + 1];
                p_lo += tanhf(acc[mi][ni][0] + b10) * w20
                      + tanhf(acc[mi][ni][1] + b11) * w21;
                p_hi += tanhf(acc[mi][ni][2] + b10) * w20
                      + tanhf(acc[mi][ni][3] + b11) * w21;
            }
            p_lo += __shfl_xor_sync(0xffffffffu, p_lo, 1);
            p_lo += __shfl_xor_sync(0xffffffffu, p_lo, 2);
            p_hi += __shfl_xor_sync(0xffffffffu, p_hi, 1);
            p_hi += __shfl_xor_sync(0xffffffffu, p_hi, 2);
            if (t == 0) {
                atomicAdd(&s_logit[row0 + mi * 16 + g], p_lo);
                atomicAdd(&s_logit[row0 + mi * 16 + 8 + g], p_hi);
            }
        }
        __syncthreads();
        if (tid < 128) {
            int gr = block_row + tid;
            if (gr < nrows) g_alog[gr] = s_logit[tid] + b2[0];
        }
    }
}

// ---------------- gather aggregation: warp per node --------------------------
__global__ void k_gather(const float* __restrict__ bias, int n) {
    if (blockIdx.x == 0 && threadIdx.x < 256) g_stats[threadIdx.x] = 0.0f;

    int node = (blockIdx.x * blockDim.x + threadIdx.x) >> 5;
    int lane = threadIdx.x & 31;
    if (node >= n) return;
    int beg = g_rowstart[node];
    int end = g_rowstart[node + 1];
    float di = g_dinv[node];

    float4 acc = ((const float4*)(g_z + (size_t)node * H))[lane];
    acc.x *= di; acc.y *= di; acc.z *= di; acc.w *= di;

    for (int base = beg; base < end; base += 32) {
        int idx = base + lane;
        int col = 0; float w = 0.0f;
        if (idx < end) { col = g_col[idx]; w = g_dinv[col]; }
        int cnt = end - base; if (cnt > 32) cnt = 32;
#pragma unroll 4
        for (int i = 0; i < cnt; i++) {
            int s = __shfl_sync(0xffffffffu, col, i);
            float ww = __shfl_sync(0xffffffffu, w, i);
            float4 v = ((const float4*)(g_z + (size_t)s * H))[lane];
            acc.x += ww * v.x;
            acc.y += ww * v.y;
            acc.z += ww * v.z;
            acc.w += ww * v.w;
        }
    }
    float4 b = ((const float4*)bias)[lane];
    acc.x = acc.x * di + b.x;
    acc.y = acc.y * di + b.y;
    acc.z = acc.z * di + b.z;
    acc.w = acc.w * di + b.w;
    ((float4*)(g_agg + (size_t)node * H))[lane] = acc;
}

// ---------------- BN ----------------------------------------------------------
__global__ void k_bn_reduce(int n) {
    int j = threadIdx.x;
    float s = 0.0f, q = 0.0f;
    for (int r = blockIdx.x; r < n; r += gridDim.x) {
        float v = g_agg[(size_t)r * H + j];
        s += v;
        q += v * v;
    }
    atomicAdd(&g_stats[j], s);
    atomicAdd(&g_stats[H + j], q);
}

__global__ void k_bn_apply(const float* __restrict__ gamma,
                           const float* __restrict__ beta, int n, int residual) {
    int idx = blockIdx.x * blockDim.x + threadIdx.x;
    if (idx >= n * H) return;
    int j = idx & (H - 1);
    float inv_n = 1.0f / (float)n;
    float mean = g_stats[j] * inv_n;
    float var = g_stats[H + j] * inv_n - mean * mean;
    float v = (g_agg[idx] - mean) * rsqrtf(var + BN_EPS) * gamma[j] + beta[j];
    v = fmaxf(v, 0.0f);
    if (residual) v += g_h[idx];
    g_h[idx] = v;
}

// ---------------- global softmax reductions -----------------------------------
__global__ void k_max_partial(int n) {
    __shared__ float sm[256];
    float m = -INFINITY;
    for (int i = blockIdx.x * blockDim.x + threadIdx.x; i < n;
         i += gridDim.x * blockDim.x)
        m = fmaxf(m, g_alog[i]);
    sm[threadIdx.x] = m;
    __syncthreads();
    for (int s = 128; s; s >>= 1) {
        if (threadIdx.x < s) sm[threadIdx.x] = fmaxf(sm[threadIdx.x], sm[threadIdx.x + s]);
        __syncthreads();
    }
    if (threadIdx.x == 0) g_part[blockIdx.x] = sm[0];
}

__global__ void k_max_final() {
    __shared__ float sm[256];
    sm[threadIdx.x] = g_part[threadIdx.x];
    __syncthreads();
    for (int s = 128; s; s >>= 1) {
        if (threadIdx.x < s) sm[threadIdx.x] = fmaxf(sm[threadIdx.x], sm[threadIdx.x + s]);
        __syncthreads();
    }
    if (threadIdx.x == 0) g_scal[0] = sm[0];
}

__global__ void k_sum_partial(int n) {
    __shared__ float sm[256];
    float gmax = g_scal[0];
    float s = 0.0f;
    for (int i = blockIdx.x * blockDim.x + threadIdx.x; i < n;
         i += gridDim.x * blockDim.x)
        s += expf(g_alog[i] - gmax);
    sm[threadIdx.x] = s;
    __syncthreads();
    for (int st = 128; st; st >>= 1) {
        if (threadIdx.x < st) sm[threadIdx.x] += sm[threadIdx.x + st];
        __syncthreads();
    }
    if (threadIdx.x == 0) g_part[blockIdx.x] = sm[0];
}

__global__ void k_sum_final() {
    __shared__ float sm[256];
    sm[threadIdx.x] = g_part[threadIdx.x];
    for (int i = threadIdx.x; i < GG * H; i += 256) g_pooled[i] = 0.0f;
    if (threadIdx.x < GG) g_counts[threadIdx.x] = 0.0f;
    __syncthreads();
    for (int st = 128; st; st >>= 1) {
        if (threadIdx.x < st) sm[threadIdx.x] += sm[threadIdx.x + st];
        __syncthreads();
    }
    if (threadIdx.x == 0) g_scal[1] = 1.0f / sm[0];
}

// ---------------- weighted mean-pool -------------------------------------------
__global__ void k_pool(const void* __restrict__ batch, int n) {
    int w = (blockIdx.x * blockDim.x + threadIdx.x) >> 5;
    int lane = threadIdx.x & 31;
    if (w >= n) return;
    float wgt = expf(g_alog[w] - g_scal[0]) * g_scal[1];
    int g = ld_idx(batch, w);
    if ((unsigned)g >= (unsigned)GG) return;
    float4 v = ((const float4*)(g_h + (size_t)w * H))[lane];
    float* p = g_pooled + (size_t)g * H + lane * 4;
    atomicAdd(p + 0, v.x * wgt);
    atomicAdd(p + 1, v.y * wgt);
    atomicAdd(p + 2, v.z * wgt);
    atomicAdd(p + 3, v.w * wgt);
    if (lane == 0) atomicAdd(&g_counts[g], 1.0f);
}

// ---------------- final MLP ------------------------------------------------------
__global__ void k_mlp(const float* __restrict__ w1, const float* __restrict__ b1,
                      const float* __restrict__ w2, const float* __restrict__ b2,
                      float* __restrict__ out) {
    int g = blockIdx.x;
    int j = threadIdx.x;
    __shared__ float p[H], t[H];
    float c = fmaxf(g_counts[g], 1.0f);
    p[j] = g_pooled[g * H + j] / c;
    __syncthreads();
    float acc = 0.0f;
#pragma unroll 8
    for (int k = 0; k < H; k++) acc += p[k] * w1[k * H + j];
    t[j] = fmaxf(acc + b1[j], 0.0f);
    __syncthreads();
    acc = 0.0f;
#pragma unroll 8
    for (int k = 0; k < H; k++) acc += t[k] * w2[k * H + j];
    out[g * H + j] = acc + b2[j];
}

// ---------------- host launcher ----------------------------------------------
extern "C" void kernel_launch(void* const* d_in, const int* in_sizes, int n_in,
                              void* d_out, int out_size) {
    int ord[32];
    int m = n_in < 32 ? n_in : 32;
    for (int i = 0; i < m; i++) ord[i] = i;
    for (int i = 1; i < m; i++) {
        int key = ord[i];
        int ks = in_sizes[key];
        int j = i - 1;
        while (j >= 0 && in_sizes[ord[j]] < ks) { ord[j + 1] = ord[j]; j--; }
        ord[j + 1] = key;
    }

    const float* x      = (const float*)d_in[ord[0]];
    const void*  ei     = d_in[ord[1]];
    const void*  batch  = d_in[ord[2]];
    const float* conv_w = (const float*)d_in[ord[3]];
    const float* aw1    = (const float*)d_in[ord[4]];
    const float* pw1    = (const float*)d_in[ord[5]];
    const float* pw2    = (const float*)d_in[ord[6]];
    const float* conv_b = (const float*)d_in[ord[7]];
    const float* bn_g   = (const float*)d_in[ord[8]];
    const float* bn_b   = (const float*)d_in[ord[9]];
    const float* ab1    = (const float*)d_in[ord[10]];
    const float* aw2    = (const float*)d_in[ord[11]];
    const float* pb1    = (const float*)d_in[ord[12]];
    const float* pb2    = (const float*)d_in[ord[13]];
    const float* ab2    = (const float*)d_in[ord[14]];
    float* out = (float*)d_out;

    const int bytes_mode = (in_sizes[ord[14]] != 1) ? 1 : 0;
    const int fbytes = bytes_mode ? 4 : 1;

    const long long x_raw  = in_sizes[ord[0]];
    const long long ei_raw = in_sizes[ord[1]];
    const int n = (int)(x_raw / (H * fbytes));
    const long long E_ub = bytes_mode ? ei_raw / 8 : ei_raw / 2;
    const long long avail64 = (bytes_mode ? ei_raw : ei_raw * 4) / 8;

    const int T = 256;
    const int gb_n   = (n + T - 1) / T;
    const int gb_e   = (int)((E_ub + T - 1) / T);
    const int gb_nh  = (n * H + T - 1) / T;
    const int gb_nw  = (n * 32 + T - 1) / T;
    const int gb_gemm = (n + 127) / 128;
    const int nb_scan = (n + SCAN_B - 1) / SCAN_B;

    // ---- index detection + CSR build ----
    k_detect<<<1, 32>>>((const long long*)ei, n, ei_raw, bytes_mode, avail64);
    k_zero_cnt<<<gb_n, T>>>(n);
    k_hist<<<gb_e, T>>>(ei, n);
    k_scan1<<<nb_scan, SCAN_B>>>(n);
    k_scan2<<<1, SCAN_B>>>(nb_scan);
    k_scan3<<<nb_scan, SCAN_B>>>(n);
    k_fill<<<gb_e, T>>>(ei, n);

    // ---- GCN layers ----
    for (int i = 0; i < 3; i++) {
        if (i == 0)
            k_gemm_tc<0, 0><<<gb_gemm, T>>>(x, conv_w, nullptr, nullptr, nullptr, n);
        else
            k_gemm_tc<1, 0><<<gb_gemm, T>>>(nullptr, conv_w + (size_t)i * H * H,
                                            nullptr, nullptr, nullptr, n);
        k_gather<<<gb_nw, T>>>(conv_b + (size_t)i * H, n);
        k_bn_reduce<<<1024, 128>>>(n);
        k_bn_apply<<<gb_nh, T>>>(bn_g + (size_t)i * H, bn_b + (size_t)i * H, n, i > 0);
    }

    // ---- attention (fused logit epilogue) ----
    k_gemm_tc<1, 1><<<gb_gemm, T>>>(nullptr, aw1, ab1, aw2, ab2, n);
    k_max_partial<<<256, 256>>>(n);
    k_max_final<<<1, 256>>>();
    k_sum_partial<<<256, 256>>>(n);
    k_sum_final<<<1, 256>>>();

    // ---- pooling + MLP ----
    k_pool<<<gb_nw, T>>>(batch, n);
    k_mlp<<<GG, H>>>(pw1, pb1, pw2, pb2, out);
}